// round 1
// baseline (speedup 1.0000x reference)
#include <cuda_runtime.h>

#define N 2048
#define D 64
#define TOTAL (N*N)          // 4194304
#define JSPLIT 8
#define JCHUNK (N/JSPLIT)    // 256
#define BM 32
#define BK 32

// ---------------- device scratch (static: no allocation allowed) ----------------
__device__ float g_pd[N*N];          // 16 MB squared-distance matrix
__device__ float g_sq[N];            // ||x_i||^2
__device__ float g_isq[N];           // 1/||x_i||^2
__device__ float g_hrn[N];           // 0.5 * rsqrt(sq)
__device__ float g_srn[N];           // sq * 0.5 * rsqrt(sq)
__device__ float g_y[N*D];           // x / ||x||
__device__ float g_c1[N*D];          // D_j s_grad_j + (1-d) x_j / sq_j
__device__ unsigned g_h1[4096];
__device__ unsigned g_h2[2*4096];
__device__ unsigned g_h3[2*256];
__device__ unsigned g_pref[2];
__device__ unsigned g_rankA[2];
__device__ unsigned g_rankB[2];
__device__ unsigned g_vbits[2];
__device__ float g_hh;
__device__ float g_pacc1[JSPLIT*N*D];
__device__ float g_pacc2[JSPLIT*N*D];
__device__ float g_prs[JSPLIT*N];

// ---------------- init: zero histograms, set median ranks ----------------
__global__ void k_init() {
    int t = blockIdx.x * blockDim.x + threadIdx.x;
    if (t < 4096) g_h1[t] = 0;
    if (t < 2*4096) g_h2[t] = 0;
    if (t < 2*256) g_h3[t] = 0;
    if (t == 0) {
        g_rankA[0] = TOTAL/2 - 1;   // 2097151
        g_rankA[1] = TOTAL/2;       // 2097152
        g_pref[0] = 0; g_pref[1] = 0;
    }
}

// ---------------- prep: per-row scalars + c1 + y (1 warp / row) ----------------
__global__ void k_prep(const float* __restrict__ x, const float* __restrict__ mu) {
    int row  = blockIdx.x * 8 + (threadIdx.x >> 5);
    int lane = threadIdx.x & 31;
    const float* xr = x + row * D;
    float x0 = xr[lane], x1 = xr[lane + 32];
    float m0 = mu[lane], m1 = mu[lane + 32];
    float dxx = x0*x0 + x1*x1;
    float dxm = x0*m0 + x1*m1;
    #pragma unroll
    for (int o = 16; o; o >>= 1) {
        dxx += __shfl_xor_sync(0xFFFFFFFFu, dxx, o);
        dxm += __shfl_xor_sync(0xFFFFFFFFu, dxm, o);
    }
    float sq  = dxx;
    float inv = 1.0f / sq;
    float rn  = rsqrtf(sq);
    // s_grad = -(x-mu);  x . s_grad = -(sq - x.mu)
    float coef = -(sq - dxm) * inv;             // (x.s_grad)/sq
    float t0 = -(x0 - m0) - x0 * coef;
    float t1 = -(x1 - m1) - x1 * coef;
    float c10 = t0 - 63.0f * x0 * inv;          // + (1-d) x/sq, d=64
    float c11 = t1 - 63.0f * x1 * inv;
    if (lane == 0) {
        g_sq[row] = sq;
        g_isq[row] = inv;
        g_hrn[row] = 0.5f * rn;
        g_srn[row] = sq * 0.5f * rn;
    }
    g_y[row*D + lane]      = x0 * rn;
    g_y[row*D + lane + 32] = x1 * rn;
    g_c1[row*D + lane]      = c10;
    g_c1[row*D + lane + 32] = c11;
}

// ---------------- pd GEMM: pd = max(sq_i + sq_j - 2 x_i.x_j, 0) ----------------
__global__ __launch_bounds__(256) void k_pd(const float* __restrict__ x) {
    __shared__ float As[64][65];     // [i][k]
    __shared__ float BsT[64][65];    // [k][j]
    int tid = threadIdx.x;
    int tx = tid & 15, ty = tid >> 4;
    int i0 = blockIdx.y * 64, j0 = blockIdx.x * 64;
    #pragma unroll
    for (int r = 0; r < 16; r++) {
        int e = tid + r * 256;           // 0..4095
        int rr = e >> 6, cc = e & 63;
        As[rr][cc]  = x[(i0 + rr) * D + cc];
        BsT[cc][rr] = x[(j0 + rr) * D + cc];
    }
    __syncthreads();
    float acc[4][4] = {};
    #pragma unroll
    for (int k = 0; k < 64; k++) {
        float a[4], b[4];
        #pragma unroll
        for (int m = 0; m < 4; m++) a[m] = As[ty*4 + m][k];
        #pragma unroll
        for (int n = 0; n < 4; n++) b[n] = BsT[k][tx*4 + n];
        #pragma unroll
        for (int m = 0; m < 4; m++)
            #pragma unroll
            for (int n = 0; n < 4; n++) acc[m][n] += a[m] * b[n];
    }
    #pragma unroll
    for (int m = 0; m < 4; m++) {
        int i = i0 + ty*4 + m;
        float si = g_sq[i];
        #pragma unroll
        for (int n = 0; n < 4; n++) {
            int j = j0 + tx*4 + n;
            float v = si + g_sq[j] - 2.0f * acc[m][n];
            g_pd[i * N + j] = fmaxf(v, 0.0f);
        }
    }
}

// ---------------- median via 3-pass radix select on float bits ----------------
__global__ void k_hist1() {
    __shared__ unsigned sh[4096];
    for (int i = threadIdx.x; i < 4096; i += 256) sh[i] = 0;
    __syncthreads();
    int stride = gridDim.x * 256;
    for (int idx = blockIdx.x * 256 + threadIdx.x; idx < TOTAL; idx += stride) {
        unsigned bits = __float_as_uint(g_pd[idx]);   // pd >= 0: bits monotone
        atomicAdd(&sh[bits >> 20], 1u);
    }
    __syncthreads();
    for (int i = threadIdx.x; i < 4096; i += 256)
        if (sh[i]) atomicAdd(&g_h1[i], sh[i]);
}

__global__ void k_hist2() {
    __shared__ unsigned sh[2][4096];
    for (int i = threadIdx.x; i < 2*4096; i += 256) ((unsigned*)sh)[i] = 0;
    __syncthreads();
    unsigned p0 = g_pref[0], p1 = g_pref[1];
    int stride = gridDim.x * 256;
    for (int idx = blockIdx.x * 256 + threadIdx.x; idx < TOTAL; idx += stride) {
        unsigned bits = __float_as_uint(g_pd[idx]);
        unsigned top = bits >> 20;
        unsigned mid = (bits >> 8) & 0xFFFu;
        if (top == p0) atomicAdd(&sh[0][mid], 1u);
        if (top == p1) atomicAdd(&sh[1][mid], 1u);
    }
    __syncthreads();
    for (int i = threadIdx.x; i < 2*4096; i += 256) {
        unsigned v = ((unsigned*)sh)[i];
        if (v) atomicAdd(&g_h2[i], v);
    }
}

__global__ void k_hist3() {
    __shared__ unsigned sh[2][256];
    for (int i = threadIdx.x; i < 2*256; i += 256) ((unsigned*)sh)[i] = 0;
    __syncthreads();
    unsigned p0 = g_pref[0], p1 = g_pref[1];       // 24-bit prefixes now
    int stride = gridDim.x * 256;
    for (int idx = blockIdx.x * 256 + threadIdx.x; idx < TOTAL; idx += stride) {
        unsigned bits = __float_as_uint(g_pd[idx]);
        unsigned top = bits >> 8;
        unsigned lo = bits & 0xFFu;
        if (top == p0) atomicAdd(&sh[0][lo], 1u);
        if (top == p1) atomicAdd(&sh[1][lo], 1u);
    }
    __syncthreads();
    for (int i = threadIdx.x; i < 2*256; i += 256) {
        unsigned v = ((unsigned*)sh)[i];
        if (v) atomicAdd(&g_h3[i], v);
    }
}

// cooperative bin select: 256 threads; finds bin containing `rank`, writes to shared
__device__ void select_bin(const unsigned* __restrict__ h, int nb, unsigned rank,
                           unsigned* sbin, unsigned* srem) {
    __shared__ unsigned psum[256];
    int t = threadIdx.x;
    int per = nb / 256;
    unsigned s = 0;
    for (int i = 0; i < per; i++) s += h[t * per + i];
    psum[t] = s;
    __syncthreads();
    if (t == 0) {
        unsigned c = 0;
        for (int i = 0; i < 256; i++) { unsigned v = psum[i]; psum[i] = c; c += v; }
    }
    __syncthreads();
    unsigned cum = psum[t];
    for (int i = 0; i < per; i++) {
        unsigned v = h[t * per + i];
        if (rank >= cum && rank < cum + v) { *sbin = (unsigned)(t * per + i); *srem = rank - cum; }
        cum += v;
    }
    __syncthreads();
}

__global__ void k_scan1() {
    __shared__ unsigned sbin, srem;
    for (int tau = 0; tau < 2; tau++) {
        unsigned rank = g_rankA[tau];
        select_bin(g_h1, 4096, rank, &sbin, &srem);
        if (threadIdx.x == 0) { g_pref[tau] = sbin; g_rankB[tau] = srem; }
        __syncthreads();
    }
}

__global__ void k_scan2() {
    __shared__ unsigned sbin, srem;
    for (int tau = 0; tau < 2; tau++) {
        unsigned rank = g_rankB[tau];
        select_bin(g_h2 + tau * 4096, 4096, rank, &sbin, &srem);
        if (threadIdx.x == 0) { g_pref[tau] = (g_pref[tau] << 12) | sbin; g_rankA[tau] = srem; }
        __syncthreads();
    }
}

__global__ void k_scan3() {
    __shared__ unsigned sbin, srem;
    for (int tau = 0; tau < 2; tau++) {
        unsigned rank = g_rankA[tau];
        select_bin(g_h3 + tau * 256, 256, rank, &sbin, &srem);
        if (threadIdx.x == 0) g_vbits[tau] = (g_pref[tau] << 8) | sbin;
        __syncthreads();
    }
    if (threadIdx.x == 0) {
        float v0 = __uint_as_float(g_vbits[0]);
        float v1 = __uint_as_float(g_vbits[1]);
        float med = 0.5f * (v0 + v1);
        g_hh = med * (1.0f / 7.6246189861593985f) + 1e-6f;   // median/ln(2048) + 1e-6
    }
}

// ---------------- main fused pass: rowsum(K), K@c1, (K.*M)@y, split over j ----------------
__global__ __launch_bounds__(256) void k_main() {
    __shared__ float sK[BM][BK + 1];
    __shared__ float sKM[BM][BK + 1];
    __shared__ float sC1[BK][D];
    __shared__ float sY[BK][D];
    int tid = threadIdx.x;
    int tx = tid & 15, ty = tid >> 4;
    int i0 = blockIdx.x * BM;
    int split = blockIdx.y;
    int jbase = split * JCHUNK;
    float inv_hh = 1.0f / g_hh;

    float acc1[2][4] = {};
    float acc2[2][4] = {};
    float rs[2] = {0.0f, 0.0f};

    int pr = tid >> 3;                 // pd tile row this thread fills
    int pc = (tid & 7) * 4;            // pd tile col (4 wide)
    float sqi_pr = g_sq[i0 + pr];

    for (int jc = 0; jc < JCHUNK; jc += BK) {
        int j0 = jbase + jc;
        __syncthreads();   // guard smem reuse across iterations
        // fill K / K*M tiles (each thread: 4 consecutive pd values, vectorized)
        {
            float4 pdv = *(const float4*)&g_pd[(i0 + pr) * N + j0 + pc];
            float pds[4] = {pdv.x, pdv.y, pdv.z, pdv.w};
            #pragma unroll
            for (int q = 0; q < 4; q++) {
                int j = j0 + pc + q;
                float kv = __expf(-pds[q] * inv_hh);
                float m = sqi_pr * g_hrn[j] + g_srn[j] - pds[q] * g_hrn[j];
                sK[pr][pc + q]  = kv;
                sKM[pr][pc + q] = kv * m;
            }
        }
        // load c1 / y chunks: 32x64 each, thread loads 8 consecutive floats
        {
            int e = tid * 8;
            int jr = e >> 6, jcol = e & 63;
            const float4* c1p = (const float4*)&g_c1[(j0 + jr) * D + jcol];
            const float4* yp  = (const float4*)&g_y[(j0 + jr) * D + jcol];
            *(float4*)&sC1[jr][jcol]     = c1p[0];
            *(float4*)&sC1[jr][jcol + 4] = c1p[1];
            *(float4*)&sY[jr][jcol]      = yp[0];
            *(float4*)&sY[jr][jcol + 4]  = yp[1];
        }
        __syncthreads();
        #pragma unroll
        for (int jj = 0; jj < BK; jj++) {
            float kv0 = sK[ty*2 + 0][jj];
            float kv1 = sK[ty*2 + 1][jj];
            float km0 = sKM[ty*2 + 0][jj];
            float km1 = sKM[ty*2 + 1][jj];
            float4 c = *(const float4*)&sC1[jj][tx*4];
            float4 yv = *(const float4*)&sY[jj][tx*4];
            acc1[0][0] += kv0 * c.x;  acc1[0][1] += kv0 * c.y;
            acc1[0][2] += kv0 * c.z;  acc1[0][3] += kv0 * c.w;
            acc1[1][0] += kv1 * c.x;  acc1[1][1] += kv1 * c.y;
            acc1[1][2] += kv1 * c.z;  acc1[1][3] += kv1 * c.w;
            acc2[0][0] += km0 * yv.x; acc2[0][1] += km0 * yv.y;
            acc2[0][2] += km0 * yv.z; acc2[0][3] += km0 * yv.w;
            acc2[1][0] += km1 * yv.x; acc2[1][1] += km1 * yv.y;
            acc2[1][2] += km1 * yv.z; acc2[1][3] += km1 * yv.w;
            if (tx == 0) { rs[0] += kv0; rs[1] += kv1; }
        }
    }
    #pragma unroll
    for (int m = 0; m < 2; m++) {
        int row = i0 + ty*2 + m;
        float* p1 = &g_pacc1[((size_t)split * N + row) * D + tx*4];
        float* p2 = &g_pacc2[((size_t)split * N + row) * D + tx*4];
        #pragma unroll
        for (int n = 0; n < 4; n++) { p1[n] = acc1[m][n]; p2[n] = acc2[m][n]; }
        if (tx == 0) g_prs[split * N + row] = rs[m];
    }
}

// ---------------- finalize: deterministic split-reduce + projection + update ----------------
__global__ void k_fin(const float* __restrict__ x, float* __restrict__ out) {
    int row  = blockIdx.x * 8 + (threadIdx.x >> 5);
    int lane = threadIdx.x & 31;
    float a10 = 0, a11 = 0, a20 = 0, a21 = 0, rstot = 0;
    #pragma unroll
    for (int s = 0; s < JSPLIT; s++) {
        const float* p1 = &g_pacc1[((size_t)s * N + row) * D];
        const float* p2 = &g_pacc2[((size_t)s * N + row) * D];
        a10 += p1[lane]; a11 += p1[lane + 32];
        a20 += p2[lane]; a21 += p2[lane + 32];
        rstot += g_prs[s * N + row];
    }
    float c2 = 2.0f / g_hh;
    float x0 = x[row * D + lane], x1 = x[row * D + lane + 32];
    float in0 = a10 + c2 * (rstot * x0 - a20);
    float in1 = a11 + c2 * (rstot * x1 - a21);
    float dot = in0 * x0 + in1 * x1;
    #pragma unroll
    for (int o = 16; o; o >>= 1) dot += __shfl_xor_sync(0xFFFFFFFFu, dot, o);
    float inv = g_isq[row];
    float g0 = in0 - x0 * (dot * inv) - x0 * (63.0f * inv);
    float g1 = in1 - x1 * (dot * inv) - x1 * (63.0f * inv);
    const float sc = 0.1f / 2048.0f;
    float d0 = fminf(fmaxf(g0 * sc, -1000.0f), 1000.0f);
    float d1 = fminf(fmaxf(g1 * sc, -1000.0f), 1000.0f);
    out[row * D + lane]      = x0 + d0;
    out[row * D + lane + 32] = x1 + d1;
}

// ---------------- launch ----------------
extern "C" void kernel_launch(void* const* d_in, const int* in_sizes, int n_in,
                              void* d_out, int out_size) {
    const float* x  = (const float*)d_in[0];   // particle [2048,64]
    const float* mu = (const float*)d_in[1];   // mu [64]
    float* out = (float*)d_out;

    k_init<<<32, 256>>>();
    k_prep<<<N / 8, 256>>>(x, mu);
    k_pd<<<dim3(N / 64, N / 64), 256>>>(x);
    k_hist1<<<512, 256>>>();
    k_scan1<<<1, 256>>>();
    k_hist2<<<512, 256>>>();
    k_scan2<<<1, 256>>>();
    k_hist3<<<512, 256>>>();
    k_scan3<<<1, 256>>>();
    k_main<<<dim3(N / BM, JSPLIT), 256>>>();
    k_fin<<<N / 8, 256>>>(x, out);
}